// round 15
// baseline (speedup 1.0000x reference)
#include <cuda_runtime.h>
#include <cuda_bf16.h>
#include <cstdint>
#include <math.h>

#define ST0 2097152ull
#define ST1 1048576ull
#define WT0_SZ (2ull * 72 * 64 * 64)
#define WT1_SZ (2ull * 72 * 128 * 128)

#define OFF_HF0A 0ull
#define OFF_HF0B (OFF_HF0A + ST0)
#define OFF_CF0  (OFF_HF0B + ST0)
#define OFF_HB0A (OFF_CF0  + ST0)
#define OFF_HB0B (OFF_HB0A + ST0)
#define OFF_CB0  (OFF_HB0B + ST0)
#define OFF_HF1A (OFF_CB0  + ST0)
#define OFF_HF1B (OFF_HF1A + ST1)
#define OFF_CF1  (OFF_HF1B + ST1)
#define OFF_HB1A (OFF_CF1  + ST1)
#define OFF_HB1B (OFF_HB1A + ST1)
#define OFF_CB1  (OFF_HB1B + ST1)
#define OFF_WTF0 (OFF_CB1  + ST1)
#define OFF_WTB0 (OFF_WTF0 + WT0_SZ)
#define OFF_WTF1 (OFF_WTB0 + WT0_SZ)
#define OFF_WTB1 (OFF_WTF1 + WT1_SZ)
#define BUF_TOTAL (OFF_WTB1 + WT1_SZ)

__device__ float g_buf[BUF_TOTAL];
#define STATE_TOTAL (OFF_WTF0)

#define XG0_CELL 134217728ull
#define XG1_CELL 67108864ull
#define XG_F0 0ull
#define XG_B0 (XG_F0 + XG0_CELL)
#define XG_F1 (XG_B0 + XG0_CELL)
#define XG_B1 (XG_F1 + XG1_CELL)
#define XG_TOTAL (XG_B1 + XG1_CELL)
__device__ float g_xg[XG_TOTAL];

__global__ void zero_kernel(float* __restrict__ p, size_t n) {
    size_t i = (size_t)blockIdx.x * blockDim.x + threadIdx.x;
    if (i < n) p[i] = 0.0f;
}

// Split each weight into (hi,lo) bf16, MMA layout (same as round 13/14).
__global__ void split_weights(const float* __restrict__ W0f, const float* __restrict__ W0b,
                              const float* __restrict__ W1f, const float* __restrict__ W1b,
                              __nv_bfloat16* __restrict__ o0f, __nv_bfloat16* __restrict__ o0b,
                              __nv_bfloat16* __restrict__ o1f, __nv_bfloat16* __restrict__ o1b)
{
    const int N0 = 294912, N1 = 1179648;
    long long j = (long long)blockIdx.x * 256 + threadIdx.x;
    const float* Wsrc; __nv_bfloat16* O; int C, N;
    if (j < N0)              { Wsrc = W0f; O = o0f; C = 64;  N = N0; }
    else if ((j -= N0) < N0) { Wsrc = W0b; O = o0b; C = 64;  N = N0; }
    else if ((j -= N0) < N1) { Wsrc = W1f; O = o1f; C = 128; N = N1; }
    else if ((j -= N1) < N1) { Wsrc = W1b; O = o1b; C = 128; N = N1; }
    else return;
    int e = (int)j;
    int k = e % 144;
    int o = (e / 144) % 64;
    int CB2 = (2 * C) / 16;
    int cib = (e / 9216) % CB2;
    int coGrp = e / (9216 * CB2);
    int tap = k >> 4, ciL = k & 15;
    int ci = cib * 16 + ciL;
    int row = (o >> 4) * C + coGrp * 16 + (o & 15);
    float w = Wsrc[((size_t)row * (2 * C) + ci) * 9 + tap];
    __nv_bfloat16 hi = __float2bfloat16(w);
    O[e] = hi;
    O[N + e] = __float2bfloat16(w - __bfloat162float(hi));
}

__device__ __forceinline__ void cpa16(unsigned dst, const void* src) {
    asm volatile("cp.async.cg.shared.global [%0], [%1], 16;" :: "r"(dst), "l"(src));
}
__device__ __forceinline__ void cpa_commit() {
    asm volatile("cp.async.commit_group;" ::: "memory");
}
__device__ __forceinline__ void mma16816(float (&d)[4], const unsigned (&a)[4],
                                         unsigned b0, unsigned b1) {
    asm volatile(
        "mma.sync.aligned.m16n8k16.row.col.f32.bf16.bf16.f32 "
        "{%0,%1,%2,%3},{%4,%5,%6,%7},{%8,%9},{%0,%1,%2,%3};"
        : "+f"(d[0]), "+f"(d[1]), "+f"(d[2]), "+f"(d[3])
        : "r"(a[0]), "r"(a[1]), "r"(a[2]), "r"(a[3]), "r"(b0), "r"(b1));
}

#define TSP 16
#define P_ELEMS (432 * 18)                   // 18x24 pixels, ci-stride 18 (bf16)
#define A_OFF2 (2 * P_ELEMS * 2)             // 31104 B (Phi + Plo)
#define A_ROW 152
#define A_BUF_B (64 * A_ROW * 2)             // 19456 B per (dbuf,half)
#define SMEM_BYTES (A_OFF2 + 4 * A_BUF_B)    // 108928 B -> 2 CTAs/SM

// ---------------------------------------------------------------------------
// MMA conv core: P built directly from gmem (LDG, coalesced), A double-buffered
// via cp.async. 2 barriers per ci-block.
// ---------------------------------------------------------------------------
template<int C, int H, int W>
__device__ __forceinline__ void conv_mma(
    const float* __restrict__ base, const __nv_bfloat16* __restrict__ Acell,
    int Ncell, int ciblkBase, int coGrp, int tileY, int tileX,
    float (&Cacc)[4][4][4])
{
    extern __shared__ char dsm[];
    __nv_bfloat16* Phi = (__nv_bfloat16*)dsm;
    __nv_bfloat16* Plo = Phi + P_ELEMS;
    char* Ab = dsm + A_OFF2;
    const unsigned sA = (unsigned)__cvta_generic_to_shared(Ab);

    const int tid = threadIdx.x;
    const int wid = tid >> 5, lane = tid & 31;
    const int g = lane >> 2, tig = lane & 3;
    const int CB2 = (2 * C) / 16, NBLK = C / 16;

    auto stageA = [&](int blk, int dbuf) {
        const size_t eb = ((size_t)coGrp * CB2 + (size_t)(ciblkBase + blk)) * 9216;
        for (int i = tid; i < 2 * 1152; i += 256) {
            const int half = i / 1152, j = i - half * 1152;
            const int row = j / 18, ch = j - row * 18;
            const __nv_bfloat16* src = Acell + (half ? Ncell : 0) + eb
                                     + row * 144 + ch * 8;
            cpa16(sA + (unsigned)((dbuf * 2 + half) * A_BUF_B
                                  + row * (A_ROW * 2) + ch * 16), src);
        }
        cpa_commit();
    };

    stageA(0, 0);

    for (int blk = 0; blk < NBLK; ++blk) {
        const int cur = blk & 1;

        // build split-bf16 patch P directly from gmem (coalesced, predicated)
        for (int i = tid; i < 3456; i += 256) {
            const int cp = i / 432;                  // ci pair 0..7
            const int pix = i - cp * 432;
            const int r = pix / 24, cc = pix - r * 24;
            const int gy = tileY - 1 + r;
            const int gx = tileX - 4 + cc;
            const bool v = (gy >= 0) && (gy < H) && (gx >= 0) && (gx < W);
            const float* p0 = base + (size_t)(blk * 16 + 2 * cp) * H * W;
            const long off = (long)gy * W + gx;
            const float v0 = v ? __ldg(p0 + off) : 0.0f;
            const float v1 = v ? __ldg(p0 + H * W + off) : 0.0f;
            __nv_bfloat162 h2 = __floats2bfloat162_rn(v0, v1);
            const float l0 = v0 - __low2float(h2);
            const float l1 = v1 - __high2float(h2);
            __nv_bfloat162 l2 = __floats2bfloat162_rn(l0, l1);
            const int pi = pix * 18 + 2 * cp;
            *(unsigned*)&Phi[pi] = *(unsigned*)&h2;
            *(unsigned*)&Plo[pi] = *(unsigned*)&l2;
        }

        if (blk + 1 < NBLK) {
            stageA(blk + 1, cur ^ 1);
            asm volatile("cp.async.wait_group 1;" ::: "memory");
        } else {
            asm volatile("cp.async.wait_group 0;" ::: "memory");
        }
        __syncthreads();                       // P + A(cur) visible

        const __nv_bfloat16* Ah = (const __nv_bfloat16*)(Ab + (cur * 2 + 0) * A_BUF_B);
        const __nv_bfloat16* Al = (const __nv_bfloat16*)(Ab + (cur * 2 + 1) * A_BUF_B);
        #pragma unroll
        for (int tap = 0; tap < 9; ++tap) {
            const int dy = tap / 3, dx = tap - dy * 3;
            const int kb = tap * 16 + 2 * tig;
            unsigned ah[4][4], al[4][4];
            #pragma unroll
            for (int m = 0; m < 4; ++m) {
                const int o = m * 16 + g;
                ah[m][0] = *(const unsigned*)&Ah[o * A_ROW + kb];
                ah[m][1] = *(const unsigned*)&Ah[(o + 8) * A_ROW + kb];
                ah[m][2] = *(const unsigned*)&Ah[o * A_ROW + kb + 8];
                ah[m][3] = *(const unsigned*)&Ah[(o + 8) * A_ROW + kb + 8];
                al[m][0] = *(const unsigned*)&Al[o * A_ROW + kb];
                al[m][1] = *(const unsigned*)&Al[(o + 8) * A_ROW + kb];
                al[m][2] = *(const unsigned*)&Al[o * A_ROW + kb + 8];
                al[m][3] = *(const unsigned*)&Al[(o + 8) * A_ROW + kb + 8];
            }
            #pragma unroll
            for (int n = 0; n < 4; ++n) {
                const int r = 2 * wid + (n >> 1) + dy;
                const int cc = (n & 1) * 8 + g + dx + 3;
                const int pb = (r * 24 + cc) * 18 + 2 * tig;
                const unsigned bh0 = *(const unsigned*)&Phi[pb];
                const unsigned bh1 = *(const unsigned*)&Phi[pb + 8];
                const unsigned bl0 = *(const unsigned*)&Plo[pb];
                const unsigned bl1 = *(const unsigned*)&Plo[pb + 8];
                #pragma unroll
                for (int m = 0; m < 4; ++m) {
                    mma16816(Cacc[m][n], ah[m], bh0, bh1);
                    mma16816(Cacc[m][n], ah[m], bl0, bl1);
                    mma16816(Cacc[m][n], al[m], bh0, bh1);
                }
            }
        }
        __syncthreads();                       // P reusable next block
    }
}

template<int C, int H, int W>
__global__ __launch_bounds__(256, 2)
void conv_x_pre(const float* __restrict__ feat, const __nv_bfloat16* __restrict__ Acell,
                int Ncell, float* __restrict__ xg, const int* __restrict__ mask)
{
    const int z = blockIdx.z;
    if (mask[z] <= 0) return;
    const int coGrp = blockIdx.y;
    const int tilesX = W / TSP, nTiles = (H / TSP) * tilesX;
    const int tileY = (blockIdx.x / tilesX) * TSP;
    const int tileX = (blockIdx.x % tilesX) * TSP;

    float Cacc[4][4][4];
    #pragma unroll
    for (int m = 0; m < 4; m++)
        #pragma unroll
        for (int n = 0; n < 4; n++)
            #pragma unroll
            for (int r = 0; r < 4; r++) Cacc[m][n][r] = 0.0f;

    conv_mma<C, H, W>(feat + (size_t)z * C * H * W, Acell, Ncell, 0, coGrp,
                      tileY, tileX, Cacc);

    float* blob = xg + (((size_t)z * (C / 16) + coGrp) * nTiles + blockIdx.x) * 16384;
    #pragma unroll
    for (int m = 0; m < 4; m++)
        #pragma unroll
        for (int n = 0; n < 4; n++)
            #pragma unroll
            for (int r = 0; r < 4; r++)
                blob[(((m * 4 + n) * 4 + r) << 8) + threadIdx.x] = Cacc[m][n][r];
}

template<int C, int H, int W>
__global__ __launch_bounds__(256, 2)
void convlstm_step(const float* __restrict__ h_in, float* __restrict__ h_out,
                   float* __restrict__ c, const __nv_bfloat16* __restrict__ Acell,
                   int Ncell, const float* __restrict__ bias,
                   const float* __restrict__ xg, const int* __restrict__ mask_t, int t)
{
    const int b = blockIdx.z;
    const int coGrp = blockIdx.y, coBase = coGrp * 16;
    const int tilesX = W / TSP, nTiles = (H / TSP) * tilesX;
    const int tileY = (blockIdx.x / tilesX) * TSP;
    const int tileX = (blockIdx.x % tilesX) * TSP;
    const int tid = threadIdx.x;

    if (mask_t[b] <= 0) {
        for (int i = tid; i < 16 * TSP * TSP; i += 256) {
            const int chL = i >> 8, rem = i & 255;
            const size_t idx = ((size_t)b * C + coBase + chL) * (size_t)(H * W)
                             + (size_t)(tileY + (rem >> 4)) * W + tileX + (rem & 15);
            h_out[idx] = h_in[idx];
        }
        return;
    }

    const int wid = tid >> 5, lane = tid & 31;
    const int g = lane >> 2, tig = lane & 3;

    float Cacc[4][4][4];
    #pragma unroll
    for (int m = 0; m < 4; m++)
        #pragma unroll
        for (int n = 0; n < 4; n++)
            #pragma unroll
            for (int r = 0; r < 4; r++) Cacc[m][n][r] = 0.0f;

    conv_mma<C, H, W>(h_in + (size_t)b * C * H * W, Acell, Ncell, C / 16, coGrp,
                      tileY, tileX, Cacc);

    const float* blob = xg +
        (((size_t)(t * 8 + b) * (C / 16) + coGrp) * nTiles + blockIdx.x) * 16384;

    #pragma unroll
    for (int hc = 0; hc < 2; hc++) {
        const int chG = coBase + g + hc * 8;
        const float bi = bias[0 * C + chG];
        const float bf = bias[1 * C + chG];
        const float bo = bias[2 * C + chG];
        const float bg = bias[3 * C + chG];
        #pragma unroll
        for (int n = 0; n < 4; n++) {
            const int py = 2 * wid + (n >> 1);
            #pragma unroll
            for (int u = 0; u < 2; u++) {
                const int r = hc * 2 + u;
                const int xx = (n & 1) * 8 + 2 * tig + u;
                const float gi = Cacc[0][n][r] + blob[(((0 * 4 + n) * 4 + r) << 8) + tid] + bi;
                const float gf = Cacc[1][n][r] + blob[(((1 * 4 + n) * 4 + r) << 8) + tid] + bf;
                const float go = Cacc[2][n][r] + blob[(((2 * 4 + n) * 4 + r) << 8) + tid] + bo;
                const float gg = Cacc[3][n][r] + blob[(((3 * 4 + n) * 4 + r) << 8) + tid] + bg;
                const size_t idx = ((size_t)b * C + chG) * (size_t)(H * W)
                                 + (size_t)(tileY + py) * W + tileX + xx;
                const float si = 1.0f / (1.0f + __expf(-gi));
                const float sf = 1.0f / (1.0f + __expf(-gf));
                const float so = 1.0f / (1.0f + __expf(-go));
                const float tg = tanhf(gg);
                const float cn = sf * c[idx] + si * tg;
                c[idx] = cn;
                h_out[idx] = so * tanhf(cn);
            }
        }
    }
}

__global__ void avg_kernel(const float* __restrict__ a, const float* __restrict__ b,
                           float* __restrict__ out, size_t n)
{
    size_t i = (size_t)blockIdx.x * blockDim.x + threadIdx.x;
    if (i < n) out[i] = 0.5f * (a[i] + b[i]);
}

extern "C" void kernel_launch(void* const* d_in, const int* in_sizes, int n_in,
                              void* d_out, int out_size)
{
    const float* feat0 = (const float*)d_in[0];
    const float* feat1 = (const float*)d_in[1];
    const int*   mask  = (const int*)  d_in[2];
    const float* Wf0   = (const float*)d_in[3];
    const float* bf0   = (const float*)d_in[4];
    const float* Wb0   = (const float*)d_in[5];
    const float* bb0   = (const float*)d_in[6];
    const float* Wf1   = (const float*)d_in[7];
    const float* bf1   = (const float*)d_in[8];
    const float* Wb1   = (const float*)d_in[9];
    const float* bb1   = (const float*)d_in[10];
    float* out = (float*)d_out;

    float* buf = nullptr;
    cudaGetSymbolAddress((void**)&buf, g_buf);
    float* xg = nullptr;
    cudaGetSymbolAddress((void**)&xg, g_xg);

    static cudaStream_t strm[3];
    static cudaEvent_t evFork, evJoin[3];
    static bool inited = false;
    if (!inited) {
        for (int i = 0; i < 3; i++)
            cudaStreamCreateWithFlags(&strm[i], cudaStreamNonBlocking);
        cudaEventCreateWithFlags(&evFork, cudaEventDisableTiming);
        for (int i = 0; i < 3; i++)
            cudaEventCreateWithFlags(&evJoin[i], cudaEventDisableTiming);
        cudaFuncSetAttribute(conv_x_pre<64, 64, 64>,
            cudaFuncAttributeMaxDynamicSharedMemorySize, SMEM_BYTES);
        cudaFuncSetAttribute(conv_x_pre<128, 32, 32>,
            cudaFuncAttributeMaxDynamicSharedMemorySize, SMEM_BYTES);
        cudaFuncSetAttribute(convlstm_step<64, 64, 64>,
            cudaFuncAttributeMaxDynamicSharedMemorySize, SMEM_BYTES);
        cudaFuncSetAttribute(convlstm_step<128, 32, 32>,
            cudaFuncAttributeMaxDynamicSharedMemorySize, SMEM_BYTES);
        inited = true;
    }

    __nv_bfloat16* A0f = (__nv_bfloat16*)(buf + OFF_WTF0);
    __nv_bfloat16* A0b = (__nv_bfloat16*)(buf + OFF_WTB0);
    __nv_bfloat16* A1f = (__nv_bfloat16*)(buf + OFF_WTF1);
    __nv_bfloat16* A1b = (__nv_bfloat16*)(buf + OFF_WTB1);
    const int N0 = 294912, N1 = 1179648;

    zero_kernel<<<(unsigned)((STATE_TOTAL + 255) / 256), 256>>>(buf, STATE_TOTAL);
    split_weights<<<11520, 256>>>(Wf0, Wb0, Wf1, Wb1, A0f, A0b, A1f, A1b);
    cudaEventRecord(evFork, 0);
    for (int i = 0; i < 3; i++) cudaStreamWaitEvent(strm[i], evFork, 0);

    const int T = 16, B = 8;
    const dim3 gridPre0(16, 4, T * B);
    const dim3 gridPre1(4, 8, T * B);
    const dim3 grid0(16, 4, B);
    const dim3 grid1(4, 8, B);

    conv_x_pre<64, 64, 64><<<gridPre0, 256, SMEM_BYTES>>>(
        feat0, A0f, N0, xg + XG_F0, mask);
    conv_x_pre<64, 64, 64><<<gridPre0, 256, SMEM_BYTES, strm[0]>>>(
        feat0, A0b, N0, xg + XG_B0, mask);
    conv_x_pre<128, 32, 32><<<gridPre1, 256, SMEM_BYTES, strm[1]>>>(
        feat1, A1f, N1, xg + XG_F1, mask);
    conv_x_pre<128, 32, 32><<<gridPre1, 256, SMEM_BYTES, strm[2]>>>(
        feat1, A1b, N1, xg + XG_B1, mask);

    float* hf0[2] = { buf + OFF_HF0A, buf + OFF_HF0B };
    float* hb0[2] = { buf + OFF_HB0A, buf + OFF_HB0B };
    float* hf1[2] = { buf + OFF_HF1A, buf + OFF_HF1B };
    float* hb1[2] = { buf + OFF_HB1A, buf + OFF_HB1B };

    for (int t = 0; t < T; ++t) {
        const int p = t & 1, q = p ^ 1;
        convlstm_step<64, 64, 64><<<grid0, 256, SMEM_BYTES>>>(
            hf0[p], hf0[q], buf + OFF_CF0, A0f, N0, bf0, xg + XG_F0, mask + t * B, t);
    }
    for (int t = 0; t < T; ++t) {
        const int p = t & 1, q = p ^ 1;
        convlstm_step<64, 64, 64><<<grid0, 256, SMEM_BYTES, strm[0]>>>(
            hb0[p], hb0[q], buf + OFF_CB0, A0b, N0, bb0, xg + XG_B0, mask + t * B, t);
    }
    for (int t = 0; t < T; ++t) {
        const int p = t & 1, q = p ^ 1;
        convlstm_step<128, 32, 32><<<grid1, 256, SMEM_BYTES, strm[1]>>>(
            hf1[p], hf1[q], buf + OFF_CF1, A1f, N1, bf1, xg + XG_F1, mask + t * B, t);
    }
    for (int t = 0; t < T; ++t) {
        const int p = t & 1, q = p ^ 1;
        convlstm_step<128, 32, 32><<<grid1, 256, SMEM_BYTES, strm[2]>>>(
            hb1[p], hb1[q], buf + OFF_CB1, A1b, N1, bb1, xg + XG_B1, mask + t * B, t);
    }

    for (int i = 0; i < 3; i++) {
        cudaEventRecord(evJoin[i], strm[i]);
        cudaStreamWaitEvent(0, evJoin[i], 0);
    }

    avg_kernel<<<(unsigned)((ST0 + 255) / 256), 256>>>(hf0[0], hb0[0], out, ST0);
    avg_kernel<<<(unsigned)((ST1 + 255) / 256), 256>>>(hf1[0], hb1[0], out + ST0, ST1);
}

// round 16
// speedup vs baseline: 1.1751x; 1.1751x over previous
#include <cuda_runtime.h>
#include <cuda_bf16.h>
#include <cstdint>
#include <math.h>

#define ST0 2097152ull            // 8*64*64*64
#define ST1 1048576ull            // 8*128*32*32
#define WT0_SZ (2ull * 72 * 64 * 64)
#define WT1_SZ (2ull * 72 * 128 * 128)

// g_buf (floats): c states + split weights
#define OFF_CF0  0ull
#define OFF_CB0  (OFF_CF0 + ST0)
#define OFF_CF1  (OFF_CB0 + ST0)
#define OFF_CB1  (OFF_CF1 + ST1)
#define OFF_WTF0 (OFF_CB1 + ST1)
#define OFF_WTB0 (OFF_WTF0 + WT0_SZ)
#define OFF_WTF1 (OFF_WTB0 + WT0_SZ)
#define OFF_WTB1 (OFF_WTF1 + WT1_SZ)
#define BUF_TOTAL (OFF_WTB1 + WT1_SZ)
__device__ float g_buf[BUF_TOTAL];
#define C_TOTAL (OFF_WTF0)        // floats to zero (c states)

// g_h (bf16): per cell [pp(2)][hi/lo(2)][S], layout [b][y][x][ch]
#define H_F0 0ull
#define H_B0 (H_F0 + 4 * ST0)
#define H_F1 (H_B0 + 4 * ST0)
#define H_B1 (H_F1 + 4 * ST1)
#define H_TOTAL (H_B1 + 4 * ST1)  // 25,165,824 bf16
__device__ __nv_bfloat16 g_h[H_TOTAL];

// g_x (bf16): split feat in [z][y][x][ch]
#define X0HI 0ull
#define X0LO (X0HI + 16 * ST0)
#define X1HI (X0LO + 16 * ST0)
#define X1LO (X1HI + 16 * ST1)
#define X_TOTAL (X1LO + 16 * ST1)
__device__ __nv_bfloat16 g_x[X_TOTAL];

// fp32 x-gate blobs, fragment layout: 16384 floats per CTA
#define XG0_CELL 134217728ull
#define XG1_CELL 67108864ull
#define XG_F0 0ull
#define XG_B0 (XG_F0 + XG0_CELL)
#define XG_F1 (XG_B0 + XG0_CELL)
#define XG_B1 (XG_F1 + XG1_CELL)
#define XG_TOTAL (XG_B1 + XG1_CELL)
__device__ float g_xg[XG_TOTAL];

__global__ void zero2_kernel(float* __restrict__ p1, size_t n1,
                             float* __restrict__ p2, size_t n2) {
    size_t i = (size_t)blockIdx.x * blockDim.x + threadIdx.x;
    if (i < n1) p1[i] = 0.0f;
    if (i < n2) p2[i] = 0.0f;
}

// Split weights into (hi,lo) bf16, MMA layout (same as R13/R14).
__global__ void split_weights(const float* __restrict__ W0f, const float* __restrict__ W0b,
                              const float* __restrict__ W1f, const float* __restrict__ W1b,
                              __nv_bfloat16* __restrict__ o0f, __nv_bfloat16* __restrict__ o0b,
                              __nv_bfloat16* __restrict__ o1f, __nv_bfloat16* __restrict__ o1b)
{
    const int N0 = 294912, N1 = 1179648;
    long long j = (long long)blockIdx.x * 256 + threadIdx.x;
    const float* Wsrc; __nv_bfloat16* O; int C, N;
    if (j < N0)              { Wsrc = W0f; O = o0f; C = 64;  N = N0; }
    else if ((j -= N0) < N0) { Wsrc = W0b; O = o0b; C = 64;  N = N0; }
    else if ((j -= N0) < N1) { Wsrc = W1f; O = o1f; C = 128; N = N1; }
    else if ((j -= N1) < N1) { Wsrc = W1b; O = o1b; C = 128; N = N1; }
    else return;
    int e = (int)j;
    int k = e % 144;
    int o = (e / 144) % 64;
    int CB2 = (2 * C) / 16;
    int cib = (e / 9216) % CB2;
    int coGrp = e / (9216 * CB2);
    int tap = k >> 4, ciL = k & 15;
    int ci = cib * 16 + ciL;
    int row = (o >> 4) * C + coGrp * 16 + (o & 15);
    float w = Wsrc[((size_t)row * (2 * C) + ci) * 9 + tap];
    __nv_bfloat16 hi = __float2bfloat16(w);
    O[e] = hi;
    O[N + e] = __float2bfloat16(w - __bfloat162float(hi));
}

// Tiled transpose + split: feat [z][C][HW] fp32 -> Xhi/Xlo [z][HW][C] bf16.
__global__ void split_x(const float* __restrict__ feat,
                        __nv_bfloat16* __restrict__ Xhi, __nv_bfloat16* __restrict__ Xlo,
                        int C, int HW)
{
    __shared__ float tile[32][65];
    const int tid = threadIdx.x;
    const int z = blockIdx.z, c0 = blockIdx.y * 32, p0 = blockIdx.x * 64;
    const float* src = feat + (size_t)z * C * HW;
    for (int i = tid; i < 2048; i += 256) {
        const int cL = i >> 6, pL = i & 63;
        tile[cL][pL] = src[(size_t)(c0 + cL) * HW + p0 + pL];
    }
    __syncthreads();
    for (int i = tid; i < 2048; i += 256) {
        const int pL = i >> 5, cL = i & 31;
        const float v = tile[cL][pL];
        const __nv_bfloat16 hi = __float2bfloat16(v);
        const size_t d = ((size_t)z * HW + p0 + pL) * C + c0 + cL;
        Xhi[d] = hi;
        Xlo[d] = __float2bfloat16(v - __bfloat162float(hi));
    }
}

__device__ __forceinline__ void cpa16(unsigned dst, const void* src) {
    asm volatile("cp.async.cg.shared.global [%0], [%1], 16;" :: "r"(dst), "l"(src));
}
__device__ __forceinline__ void cpa16z(unsigned dst, const void* src, bool v) {
    int sz = v ? 16 : 0;
    asm volatile("cp.async.cg.shared.global [%0], [%1], 16, %2;"
                 :: "r"(dst), "l"(src), "r"(sz));
}
__device__ __forceinline__ void cpa_commit() {
    asm volatile("cp.async.commit_group;" ::: "memory");
}
__device__ __forceinline__ void mma16816(float (&d)[4], const unsigned (&a)[4],
                                         unsigned b0, unsigned b1) {
    asm volatile(
        "mma.sync.aligned.m16n8k16.row.col.f32.bf16.bf16.f32 "
        "{%0,%1,%2,%3},{%4,%5,%6,%7},{%8,%9},{%0,%1,%2,%3};"
        : "+f"(d[0]), "+f"(d[1]), "+f"(d[2]), "+f"(d[3])
        : "r"(a[0]), "r"(a[1]), "r"(a[2]), "r"(a[3]), "r"(b0), "r"(b1));
}

#define TSP 16
#define PSTR 24                         // ci stride in P (bf16): 16 data + 8 pad
#define P_BUF_B (432 * PSTR * 2)        // 20736 B per array (hi or lo)
#define A_OFF2 (2 * P_BUF_B)            // 41472
#define A_ROW 152
#define A_BUF_B (64 * A_ROW * 2)        // 19456 B per half
#define SMEM_BYTES (A_OFF2 + 2 * A_BUF_B)  // 80384 B -> 2 CTAs/SM

// ---------------------------------------------------------------------------
// MMA conv core: input already split-bf16 in [pixel][C] layout (bHi/bLo).
// Stage P + A via cp.async; 2 barriers per ci-block; no conversion phase.
// ---------------------------------------------------------------------------
template<int C, int H, int W>
__device__ __forceinline__ void conv_mma(
    const __nv_bfloat16* __restrict__ bHi, const __nv_bfloat16* __restrict__ bLo,
    const __nv_bfloat16* __restrict__ Acell, int Ncell,
    int cibBase, int coGrp, int tileY, int tileX, float (&Cacc)[4][4][4])
{
    extern __shared__ char dsm[];
    __nv_bfloat16* Phi = (__nv_bfloat16*)dsm;
    __nv_bfloat16* Plo = (__nv_bfloat16*)(dsm + P_BUF_B);
    char* Ab = dsm + A_OFF2;
    const unsigned sP = (unsigned)__cvta_generic_to_shared(dsm);
    const unsigned sA = (unsigned)__cvta_generic_to_shared(Ab);

    const int tid = threadIdx.x;
    const int wid = tid >> 5, lane = tid & 31;
    const int g = lane >> 2, tig = lane & 3;
    const int CB2 = (2 * C) / 16, NBLK = C / 16;

    for (int blk = 0; blk < NBLK; ++blk) {
        __syncthreads();                     // prev MMA done; P/A reusable
        // stage P: 432 pixels x 2 chunks x {hi,lo}
        for (int i = tid; i < 1728; i += 256) {
            const int arr = i / 864, rem = i - arr * 864;
            const int pix = rem >> 1, q = rem & 1;
            const int r = pix / 24, cc = pix - r * 24;
            const int gy = tileY - 1 + r, gx = tileX - 4 + cc;
            const bool v = (gy >= 0) && (gy < H) && (gx >= 0) && (gx < W);
            const __nv_bfloat16* src = (arr ? bLo : bHi)
                + (size_t)(v ? (gy * W + gx) : 0) * C + blk * 16 + q * 8;
            cpa16z(sP + (unsigned)(arr * P_BUF_B + pix * (PSTR * 2) + q * 16), src, v);
        }
        // stage A (hi+lo halves)
        {
            const size_t eb = ((size_t)coGrp * CB2 + (size_t)(cibBase + blk)) * 9216;
            for (int i = tid; i < 2304; i += 256) {
                const int half = i / 1152, j = i - half * 1152;
                const int row = j / 18, ch = j - row * 18;
                const __nv_bfloat16* src = Acell + (half ? Ncell : 0) + eb
                                         + row * 144 + ch * 8;
                cpa16(sA + (unsigned)(half * A_BUF_B + row * (A_ROW * 2) + ch * 16), src);
            }
        }
        cpa_commit();
        asm volatile("cp.async.wait_group 0;" ::: "memory");
        __syncthreads();                     // P + A visible

        const __nv_bfloat16* Ah = (const __nv_bfloat16*)(Ab);
        const __nv_bfloat16* Al = (const __nv_bfloat16*)(Ab + A_BUF_B);
        #pragma unroll
        for (int tap = 0; tap < 9; ++tap) {
            const int dy = tap / 3, dx = tap - dy * 3;
            const int kb = tap * 16 + 2 * tig;
            unsigned ah[4][4], al[4][4];
            #pragma unroll
            for (int m = 0; m < 4; ++m) {
                const int o = m * 16 + g;
                ah[m][0] = *(const unsigned*)&Ah[o * A_ROW + kb];
                ah[m][1] = *(const unsigned*)&Ah[(o + 8) * A_ROW + kb];
                ah[m][2] = *(const unsigned*)&Ah[o * A_ROW + kb + 8];
                ah[m][3] = *(const unsigned*)&Ah[(o + 8) * A_ROW + kb + 8];
                al[m][0] = *(const unsigned*)&Al[o * A_ROW + kb];
                al[m][1] = *(const unsigned*)&Al[(o + 8) * A_ROW + kb];
                al[m][2] = *(const unsigned*)&Al[o * A_ROW + kb + 8];
                al[m][3] = *(const unsigned*)&Al[(o + 8) * A_ROW + kb + 8];
            }
            #pragma unroll
            for (int n = 0; n < 4; ++n) {
                const int r = 2 * wid + (n >> 1) + dy;
                const int cc = (n & 1) * 8 + g + dx + 3;
                const int pb = (r * 24 + cc) * PSTR + 2 * tig;
                const unsigned bh0 = *(const unsigned*)&Phi[pb];
                const unsigned bh1 = *(const unsigned*)&Phi[pb + 8];
                const unsigned bl0 = *(const unsigned*)&Plo[pb];
                const unsigned bl1 = *(const unsigned*)&Plo[pb + 8];
                #pragma unroll
                for (int m = 0; m < 4; ++m) {
                    mma16816(Cacc[m][n], ah[m], bh0, bh1);
                    mma16816(Cacc[m][n], ah[m], bl0, bl1);
                    mma16816(Cacc[m][n], al[m], bh0, bh1);
                }
            }
        }
    }
}

template<int C, int H, int W>
__global__ __launch_bounds__(256, 2)
void conv_x_pre(const __nv_bfloat16* __restrict__ Xhi,
                const __nv_bfloat16* __restrict__ Xlo,
                const __nv_bfloat16* __restrict__ Acell, int Ncell,
                float* __restrict__ xg, const int* __restrict__ mask)
{
    const int z = blockIdx.z;
    if (mask[z] <= 0) return;
    const int coGrp = blockIdx.y;
    const int tilesX = W / TSP, nTiles = (H / TSP) * tilesX;
    const int tileY = (blockIdx.x / tilesX) * TSP;
    const int tileX = (blockIdx.x % tilesX) * TSP;

    float Cacc[4][4][4];
    #pragma unroll
    for (int m = 0; m < 4; m++)
        #pragma unroll
        for (int n = 0; n < 4; n++)
            #pragma unroll
            for (int r = 0; r < 4; r++) Cacc[m][n][r] = 0.0f;

    const size_t zb = (size_t)z * H * W * C;
    conv_mma<C, H, W>(Xhi + zb, Xlo + zb, Acell, Ncell, 0, coGrp, tileY, tileX, Cacc);

    float* blob = xg + (((size_t)z * (C / 16) + coGrp) * nTiles + blockIdx.x) * 16384;
    #pragma unroll
    for (int m = 0; m < 4; m++)
        #pragma unroll
        for (int n = 0; n < 4; n++)
            #pragma unroll
            for (int r = 0; r < 4; r++)
                blob[(((m * 4 + n) * 4 + r) << 8) + threadIdx.x] = Cacc[m][n][r];
}

template<int C, int H, int W>
__global__ __launch_bounds__(256, 2)
void convlstm_step(const __nv_bfloat16* __restrict__ hhi_in,
                   const __nv_bfloat16* __restrict__ hlo_in,
                   __nv_bfloat16* __restrict__ hhi_out,
                   __nv_bfloat16* __restrict__ hlo_out,
                   float* __restrict__ c,
                   const __nv_bfloat16* __restrict__ Acell, int Ncell,
                   const float* __restrict__ bias,
                   const float* __restrict__ xg, const int* __restrict__ mask_t, int t)
{
    const int b = blockIdx.z;
    const int coGrp = blockIdx.y, coBase = coGrp * 16;
    const int tilesX = W / TSP, nTiles = (H / TSP) * tilesX;
    const int tileY = (blockIdx.x / tilesX) * TSP;
    const int tileX = (blockIdx.x % tilesX) * TSP;
    const int tid = threadIdx.x;
    const size_t bb = (size_t)b * H * W * C;

    if (mask_t[b] <= 0) {
        // copy owned 16-ch slice (hi+lo), uint granularity (8 uints/pixel/array)
        for (int i = tid; i < 4096; i += 256) {
            const int arr = i >> 11, rem = i & 2047;
            const int pix = rem >> 3, u = rem & 7;
            const int gy = tileY + (pix >> 4), gx = tileX + (pix & 15);
            const size_t e = bb + (size_t)(gy * W + gx) * C + coBase;
            const unsigned* s = (const unsigned*)((arr ? hlo_in : hhi_in) + e);
            unsigned* d = (unsigned*)((arr ? hlo_out : hhi_out) + e);
            d[u] = s[u];
        }
        return;
    }

    const int wid = tid >> 5, lane = tid & 31;
    const int g = lane >> 2, tig = lane & 3;

    float Cacc[4][4][4];
    #pragma unroll
    for (int m = 0; m < 4; m++)
        #pragma unroll
        for (int n = 0; n < 4; n++)
            #pragma unroll
            for (int r = 0; r < 4; r++) Cacc[m][n][r] = 0.0f;

    conv_mma<C, H, W>(hhi_in + bb, hlo_in + bb, Acell, Ncell, C / 16, coGrp,
                      tileY, tileX, Cacc);

    const float* blob = xg +
        (((size_t)(t * 8 + b) * (C / 16) + coGrp) * nTiles + blockIdx.x) * 16384;

    #pragma unroll
    for (int hc = 0; hc < 2; hc++) {
        const int chG = coBase + g + hc * 8;
        const float bi = bias[0 * C + chG];
        const float bf = bias[1 * C + chG];
        const float bo = bias[2 * C + chG];
        const float bg = bias[3 * C + chG];
        #pragma unroll
        for (int n = 0; n < 4; n++) {
            const int py = 2 * wid + (n >> 1);
            #pragma unroll
            for (int u = 0; u < 2; u++) {
                const int r = hc * 2 + u;
                const int xx = (n & 1) * 8 + 2 * tig + u;
                const float gi = Cacc[0][n][r] + blob[(((0 * 4 + n) * 4 + r) << 8) + tid] + bi;
                const float gf = Cacc[1][n][r] + blob[(((1 * 4 + n) * 4 + r) << 8) + tid] + bf;
                const float go = Cacc[2][n][r] + blob[(((2 * 4 + n) * 4 + r) << 8) + tid] + bo;
                const float gg = Cacc[3][n][r] + blob[(((3 * 4 + n) * 4 + r) << 8) + tid] + bg;
                const size_t idx = bb + (size_t)((tileY + py) * W + tileX + xx) * C + chG;
                const float si = 1.0f / (1.0f + __expf(-gi));
                const float sf = 1.0f / (1.0f + __expf(-gf));
                const float so = 1.0f / (1.0f + __expf(-go));
                const float tg = tanhf(gg);
                const float cn = sf * c[idx] + si * tg;
                c[idx] = cn;
                const float hn = so * tanhf(cn);
                const __nv_bfloat16 hi = __float2bfloat16(hn);
                hhi_out[idx] = hi;
                hlo_out[idx] = __float2bfloat16(hn - __bfloat162float(hi));
            }
        }
    }
}

// Final average: read NHWC split pairs, write NCHW fp32.
__global__ void avg_kernel(const __nv_bfloat16* __restrict__ fhi,
                           const __nv_bfloat16* __restrict__ flo,
                           const __nv_bfloat16* __restrict__ bhi,
                           const __nv_bfloat16* __restrict__ blo,
                           float* __restrict__ out, int C, int HW, size_t n)
{
    size_t i = (size_t)blockIdx.x * blockDim.x + threadIdx.x;
    if (i >= n) return;
    const int b = (int)(i / ((size_t)C * HW));
    const int rem = (int)(i - (size_t)b * C * HW);
    const int ch = rem / HW, pix = rem - ch * HW;
    const size_t s = ((size_t)b * HW + pix) * C + ch;
    const float hf = __bfloat162float(fhi[s]) + __bfloat162float(flo[s]);
    const float hb = __bfloat162float(bhi[s]) + __bfloat162float(blo[s]);
    out[i] = 0.5f * (hf + hb);
}

extern "C" void kernel_launch(void* const* d_in, const int* in_sizes, int n_in,
                              void* d_out, int out_size)
{
    const float* feat0 = (const float*)d_in[0];
    const float* feat1 = (const float*)d_in[1];
    const int*   mask  = (const int*)  d_in[2];
    const float* Wf0   = (const float*)d_in[3];
    const float* bf0   = (const float*)d_in[4];
    const float* Wb0   = (const float*)d_in[5];
    const float* bb0   = (const float*)d_in[6];
    const float* Wf1   = (const float*)d_in[7];
    const float* bf1   = (const float*)d_in[8];
    const float* Wb1   = (const float*)d_in[9];
    const float* bb1   = (const float*)d_in[10];
    float* out = (float*)d_out;

    float* buf = nullptr;  cudaGetSymbolAddress((void**)&buf, g_buf);
    float* xg = nullptr;   cudaGetSymbolAddress((void**)&xg, g_xg);
    __nv_bfloat16* hbuf = nullptr; cudaGetSymbolAddress((void**)&hbuf, g_h);
    __nv_bfloat16* xbuf = nullptr; cudaGetSymbolAddress((void**)&xbuf, g_x);

    static cudaStream_t strm[3];
    static cudaEvent_t evFork, evJoin[3];
    static bool inited = false;
    if (!inited) {
        for (int i = 0; i < 3; i++)
            cudaStreamCreateWithFlags(&strm[i], cudaStreamNonBlocking);
        cudaEventCreateWithFlags(&evFork, cudaEventDisableTiming);
        for (int i = 0; i < 3; i++)
            cudaEventCreateWithFlags(&evJoin[i], cudaEventDisableTiming);
        cudaFuncSetAttribute(conv_x_pre<64, 64, 64>,
            cudaFuncAttributeMaxDynamicSharedMemorySize, SMEM_BYTES);
        cudaFuncSetAttribute(conv_x_pre<128, 32, 32>,
            cudaFuncAttributeMaxDynamicSharedMemorySize, SMEM_BYTES);
        cudaFuncSetAttribute(convlstm_step<64, 64, 64>,
            cudaFuncAttributeMaxDynamicSharedMemorySize, SMEM_BYTES);
        cudaFuncSetAttribute(convlstm_step<128, 32, 32>,
            cudaFuncAttributeMaxDynamicSharedMemorySize, SMEM_BYTES);
        inited = true;
    }

    __nv_bfloat16* A0f = (__nv_bfloat16*)(buf + OFF_WTF0);
    __nv_bfloat16* A0b = (__nv_bfloat16*)(buf + OFF_WTB0);
    __nv_bfloat16* A1f = (__nv_bfloat16*)(buf + OFF_WTF1);
    __nv_bfloat16* A1b = (__nv_bfloat16*)(buf + OFF_WTB1);
    const int N0 = 294912, N1 = 1179648;

    // prelude: zero (c + h-as-float), split weights, split x
    {
        const size_t nH = H_TOTAL / 2;   // bf16 pairs as floats
        const size_t nz = (C_TOTAL > nH ? C_TOTAL : nH);
        zero2_kernel<<<(unsigned)((nz + 255) / 256), 256>>>(buf, C_TOTAL,
                                                            (float*)hbuf, nH);
    }
    split_weights<<<11520, 256>>>(Wf0, Wb0, Wf1, Wb1, A0f, A0b, A1f, A1b);
    split_x<<<dim3(64, 2, 128), 256>>>(feat0, xbuf + X0HI, xbuf + X0LO, 64, 4096);
    split_x<<<dim3(16, 4, 128), 256>>>(feat1, xbuf + X1HI, xbuf + X1LO, 128, 1024);
    cudaEventRecord(evFork, 0);
    for (int i = 0; i < 3; i++) cudaStreamWaitEvent(strm[i], evFork, 0);

    const int T = 16, B = 8;
    const dim3 gridPre0(16, 4, T * B);
    const dim3 gridPre1(4, 8, T * B);
    const dim3 grid0(16, 4, B);
    const dim3 grid1(4, 8, B);

    conv_x_pre<64, 64, 64><<<gridPre0, 256, SMEM_BYTES>>>(
        xbuf + X0HI, xbuf + X0LO, A0f, N0, xg + XG_F0, mask);
    conv_x_pre<64, 64, 64><<<gridPre0, 256, SMEM_BYTES, strm[0]>>>(
        xbuf + X0HI, xbuf + X0LO, A0b, N0, xg + XG_B0, mask);
    conv_x_pre<128, 32, 32><<<gridPre1, 256, SMEM_BYTES, strm[1]>>>(
        xbuf + X1HI, xbuf + X1LO, A1f, N1, xg + XG_F1, mask);
    conv_x_pre<128, 32, 32><<<gridPre1, 256, SMEM_BYTES, strm[2]>>>(
        xbuf + X1HI, xbuf + X1LO, A1b, N1, xg + XG_B1, mask);

    // h buffers: per cell [pp][hi/lo][S]
    __nv_bfloat16* HF0 = hbuf + H_F0;
    __nv_bfloat16* HB0 = hbuf + H_B0;
    __nv_bfloat16* HF1 = hbuf + H_F1;
    __nv_bfloat16* HB1 = hbuf + H_B1;

    for (int t = 0; t < T; ++t) {
        const int p = t & 1, q = p ^ 1;
        convlstm_step<64, 64, 64><<<grid0, 256, SMEM_BYTES>>>(
            HF0 + p * 2 * ST0, HF0 + p * 2 * ST0 + ST0,
            HF0 + q * 2 * ST0, HF0 + q * 2 * ST0 + ST0,
            buf + OFF_CF0, A0f, N0, bf0, xg + XG_F0, mask + t * B, t);
    }
    for (int t = 0; t < T; ++t) {
        const int p = t & 1, q = p ^ 1;
        convlstm_step<64, 64, 64><<<grid0, 256, SMEM_BYTES, strm[0]>>>(
            HB0 + p * 2 * ST0, HB0 + p * 2 * ST0 + ST0,
            HB0 + q * 2 * ST0, HB0 + q * 2 * ST0 + ST0,
            buf + OFF_CB0, A0b, N0, bb0, xg + XG_B0, mask + t * B, t);
    }
    for (int t = 0; t < T; ++t) {
        const int p = t & 1, q = p ^ 1;
        convlstm_step<128, 32, 32><<<grid1, 256, SMEM_BYTES, strm[1]>>>(
            HF1 + p * 2 * ST1, HF1 + p * 2 * ST1 + ST1,
            HF1 + q * 2 * ST1, HF1 + q * 2 * ST1 + ST1,
            buf + OFF_CF1, A1f, N1, bf1, xg + XG_F1, mask + t * B, t);
    }
    for (int t = 0; t < T; ++t) {
        const int p = t & 1, q = p ^ 1;
        convlstm_step<128, 32, 32><<<grid1, 256, SMEM_BYTES, strm[2]>>>(
            HB1 + p * 2 * ST1, HB1 + p * 2 * ST1 + ST1,
            HB1 + q * 2 * ST1, HB1 + q * 2 * ST1 + ST1,
            buf + OFF_CB1, A1b, N1, bb1, xg + XG_B1, mask + t * B, t);
    }

    for (int i = 0; i < 3; i++) {
        cudaEventRecord(evJoin[i], strm[i]);
        cudaStreamWaitEvent(0, evJoin[i], 0);
    }

    // T=16 even: final states in ping (pp=0) buffers.
    avg_kernel<<<(unsigned)((ST0 + 255) / 256), 256>>>(
        HF0, HF0 + ST0, HB0, HB0 + ST0, out, 64, 64 * 64, ST0);
    avg_kernel<<<(unsigned)((ST1 + 255) / 256), 256>>>(
        HF1, HF1 + ST1, HB1, HB1 + ST1, out + ST0, 128, 32 * 32, ST1);
}